// round 11
// baseline (speedup 1.0000x reference)
#include <cuda_runtime.h>

// Problem constants (fixed by the reference).
#define B_DIM   16384
#define T_DIM   512
#define HOR     32
#define NSTEP   (T_DIM + B_DIM - 1)   // 16895 scan steps
#define NPAD    16896                 // 132 * 128
#define NBLK    132                   // chunks of 128 steps (= queue depth M)
#define NGRP    33                    // groups of 4 chunks

// Scratch (__device__ globals; zero-initialized).
__device__ float g_ts[NPAD];
__device__ float g_xnorm[NPAD];
__device__ float g_levels[NPAD];
__device__ float g_sseq[NPAD];
__device__ int   g_gcnt[NGRP];        // per-group producer counters (0..4)

__device__ __forceinline__ float frcp(float x) {
    float r;
    asm("rcp.approx.ftz.f32 %0, %1;" : "=f"(r) : "f"(x));
    return r;
}
__device__ __forceinline__ void wait_group(int grp) {
    const volatile int* vp = (const volatile int*)&g_gcnt[grp];
    while (*vp < 4) { }
    __threadfence();                  // acquire: order g_ts reads below
}

// Warp-0 scan body for one 128-step block. I becomes the TRUE level at this
// lane's last step (carry folded into lane0's input); l2,l1,l0 backward.
// No xnorm and no sseq store here (warp 1's job).
#define SCAN_BODY(BLK, PIDX)                                                   \
  {                                                                            \
    const int base = (BLK) * 128 + t0;                                         \
    const float4 yf = *reinterpret_cast<const float4*>(g_ts + (PIDX));         \
    const float t1raw = fmaf(k, c2, c3);                                       \
    const float t2e   = fmaf(k, c0, c1);                                       \
    const float t1    = (lane == 0) ? fmaf(k4, Tc, t1raw) : t1raw;             \
    float I = fmaf(k2, t2e, t1);                                               \
    float tsh;                                                                 \
    tsh = __shfl_up_sync(FULL, I, 1);  if (lane >= 1)  I = fmaf(K0,  tsh, I);  \
    tsh = __shfl_up_sync(FULL, I, 2);  if (lane >= 2)  I = fmaf(K1,  tsh, I);  \
    tsh = __shfl_up_sync(FULL, I, 4);  if (lane >= 4)  I = fmaf(K2c, tsh, I);  \
    tsh = __shfl_up_sync(FULL, I, 8);  if (lane >= 8)  I = fmaf(K3,  tsh, I);  \
    tsh = __shfl_up_sync(FULL, I, 16); if (lane >= 16) I = fmaf(K4,  tsh, I);  \
    const float l3 = I;                                                        \
    const float l2 = fmaf(rk, l3, ncrk3);                                      \
    const float l1 = fmaf(rk, l2, ncrk2);                                      \
    const float l0 = fmaf(rk, l1, ncrk1);                                      \
    const float d1 = fmaf(os1, l1, gy1);                                       \
    const float rd1 = frcp(d1);                                                \
    const float d0 = fmaf(os0, l0, gy0);                                       \
    const float rd0 = frcp(d0);                                                \
    const float d2 = fmaf(os2, l2, gy2);                                       \
    const float d3 = fmaf(os3, l3, gy3);                                       \
    const float rd2 = frcp(d2), rd3 = frcp(d3);                                \
    const float nc0 = (ay0 * l0) * rd0, nc1 = (ay1 * l1) * rd1;                \
    const float nc2 = (ay2 * l2) * rd2, nc3 = (ay3 * l3) * rd3;                \
    Tc = __shfl_sync(FULL, I, 31);                                             \
    *reinterpret_cast<float4*>(g_levels + base) = make_float4(l0, l1, l2, l3); \
    /* os' = omg * s_new = omg * d * rcp(l): recurrence state, no store */     \
    const float rl0 = frcp(l0), rl1 = frcp(l1), rl2 = frcp(l2), rl3 = frcp(l3);\
    os0 = omg * (d0 * rl0); os1 = omg * (d1 * rl1);                            \
    os2 = omg * (d2 * rl2); os3 = omg * (d3 * rl3);                            \
    c0 = nc0; c1 = nc1; c2 = nc2; c3 = nc3;                                    \
    ncrk1 = -(nc1 * rk); ncrk2 = -(nc2 * rk); ncrk3 = -(nc3 * rk);             \
    gy0 = rga * ay0; gy1 = rga * ay1; gy2 = rga * ay2; gy3 = rga * ay3;        \
    ay0 = a * ynn.x; ay1 = a * ynn.y; ay2 = a * ynn.z; ay3 = a * ynn.w;        \
    ynn = yf;                                                                  \
  }

// ---------------------------------------------------------------------------
// Fused gather + scan. Grid = 133 x 64 (all resident; proven R7/R8).
//  blocks 1..132 : gather chunk (bid-1) of the effective series, then bump
//                  the group counter (4 chunks per group).
//  block 0 warp 0: Kogge-Stone blocked linear scan; spins ONCE per 4-block
//                  group on the counter (outside the branch-free inner loop);
//                  publishes smem progress for warp 1.
//  block 0 warp 1: lags behind; computes x_norm = y*rcp(s*l) AND the sseq
//                  store (s_new = g*y*rcp(l) + (1-g)*s_old) from g_ts,
//                  g_levels, and its own prior sseq store.
// Scanner resets g_gcnt at the end (all producers provably done).
// ---------------------------------------------------------------------------
__global__ void __launch_bounds__(64, 1)
scan_kernel(const float* __restrict__ x,
            const float* __restrict__ alpha, const float* __restrict__ gamma,
            const float* __restrict__ init_s, const float* __restrict__ level0) {
    const int bid = blockIdx.x;
    const int tid = threadIdx.x;

    if (bid != 0) {
        // ---- producer: gather one 128-element chunk (2 elements/thread).
        const int j = bid - 1;
        #pragma unroll
        for (int e = 0; e < 2; ++e) {
            const int i = j * 128 + tid * 2 + e;
            float v;
            if (i < T_DIM)       v = __ldg(x + i);
            else if (i < NSTEP)  v = __ldg(x + (i - (T_DIM - 1)) * T_DIM + (T_DIM - 1));
            else                 v = 1.0f;
            g_ts[i] = v;
        }
        __threadfence();                  // release my stores
        __syncthreads();
        if (tid == 0) atomicAdd(&g_gcnt[j >> 2], 1);
        return;
    }

    // ======================= block 0: scan + xnorm =======================
    __shared__ int s_cnt;                 // # of scan blocks with levels stored
    const unsigned FULL = 0xFFFFFFFFu;
    const int lane = tid & 31;
    const int t0 = lane * 4;
    if (tid == 0) s_cnt = 0;
    __syncthreads();

    if (tid >= 32) {
        // ---- warp 1: x_norm + sseq consumer (lags warp 0 by <= 4 blocks).
        const float g   = gamma[0];
        const float omg = 1.0f - g;
        volatile int* vc = &s_cnt;
        float4 s4 = *reinterpret_cast<const float4*>(init_s + t0);
        #pragma unroll 1
        for (int blk = 0; blk < NBLK; ++blk) {
            while (*vc < blk + 1) { }
            __threadfence_block();        // acquire
            const int base = blk * 128 + t0;
            float4 y4 = *reinterpret_cast<const float4*>(g_ts + base);
            float4 l4 = *reinterpret_cast<const float4*>(g_levels + base);
            float4 o;                     // x_norm = y * rcp(s_old * l)
            o.x = y4.x * frcp(s4.x * l4.x);
            o.y = y4.y * frcp(s4.y * l4.y);
            o.z = y4.z * frcp(s4.z * l4.z);
            o.w = y4.w * frcp(s4.w * l4.w);
            *reinterpret_cast<float4*>(g_xnorm + base) = o;
            float4 sn;                    // s_new = g*y*rcp(l) + (1-g)*s_old
            sn.x = fmaf(omg, s4.x, (g * y4.x) * frcp(l4.x));
            sn.y = fmaf(omg, s4.y, (g * y4.y) * frcp(l4.y));
            sn.z = fmaf(omg, s4.z, (g * y4.z) * frcp(l4.z));
            sn.w = fmaf(omg, s4.w, (g * y4.w) * frcp(l4.w));
            *reinterpret_cast<float4*>(g_sseq + base) = sn;
            s4 = sn;                      // self-feeding queue (distance 128)
        }
        return;
    }

    // ---- warp 0: scanner.
    const float a   = alpha[0];
    const float g   = gamma[0];
    const float k   = 1.0f - a;
    const float omg = 1.0f - g;
    const float k2 = k * k, k4 = k2 * k2;
    const float rk = 1.0f / k;
    const float rga = g / a;               // gy_next = (g/a) * ay
    const float K0 = k4, K1 = K0 * K0, K2c = K1 * K1, K3 = K2c * K2c, K4 = K3 * K3;

    float Tc = level0[0];

    wait_group(0);                         // chunks 0..3
    float4 yv  = *reinterpret_cast<const float4*>(g_ts + t0);
    float4 ynv = *reinterpret_cast<const float4*>(g_ts + 128 + t0);
    float4 ynn = *reinterpret_cast<const float4*>(g_ts + 256 + t0);

    float4 sv = *reinterpret_cast<const float4*>(init_s + t0);
    float c0 = (a * yv.x) * frcp(sv.x), c1 = (a * yv.y) * frcp(sv.y);
    float c2 = (a * yv.z) * frcp(sv.z), c3 = (a * yv.w) * frcp(sv.w);
    float ncrk1 = -(c1 * rk), ncrk2 = -(c2 * rk), ncrk3 = -(c3 * rk);
    float gy0 = g * yv.x, gy1 = g * yv.y, gy2 = g * yv.z, gy3 = g * yv.w;
    float os0 = omg * sv.x, os1 = omg * sv.y, os2 = omg * sv.z, os3 = omg * sv.w;
    float ay0 = a * ynv.x, ay1 = a * ynv.y, ay2 = a * ynv.z, ay3 = a * ynv.w;

    // Main: 32 groups of 4 blocks. One spin per group (covers prefetches up
    // to chunk 4*grp+6), branch-free inner body, one progress publish.
    #pragma unroll 1
    for (int grp = 0; grp < 32; ++grp) {
        wait_group(grp + 1);
        #pragma unroll
        for (int u = 0; u < 4; ++u) {
            const int blk = grp * 4 + u;
            SCAN_BODY(blk, blk * 128 + t0 + 384);
        }
        __threadfence_block();
        if (lane == 0) *(volatile int*)&s_cnt = grp * 4 + 4;
    }

    // Tail blocks 128..131 (group 32 already waited; prefetch clamped).
    SCAN_BODY(128, 128 * 128 + t0 + 384);
    SCAN_BODY(129, t0);
    SCAN_BODY(130, t0);
    SCAN_BODY(131, t0);
    __threadfence_block();
    if (lane == 0) *(volatile int*)&s_cnt = NBLK;

    // Self-clean for graph replay (all 33 groups observed complete).
    for (int j2 = lane; j2 < NGRP; j2 += 32) g_gcnt[j2] = 0;
}

// ---------------------------------------------------------------------------
// Materialize outputs. x-part: thread's window B equals the NEXT thread's A
// -> fetch via 3 shfl_down; only lane 31 does the real second load. Cuts
// load wavefronts ~8 -> ~5 per warp on an L1-wavefront-bound kernel.
// ---------------------------------------------------------------------------
#define XTASKS ((B_DIM / 4) * (T_DIM / 4))     // 524288
#define DTASKS (B_DIM * (HOR / 2))             // 262144

__global__ void __launch_bounds__(256)
out_kernel(float* __restrict__ out) {
    const unsigned FULL = 0xFFFFFFFFu;
    const float4* __restrict__ X4 = reinterpret_cast<const float4*>(g_xnorm);
    int gid = blockIdx.x * blockDim.x + threadIdx.x;
    if (gid < XTASKS) {
        const int b4 = gid >> 7;          // row group (4 rows); warp never
        const int q  = gid & 127;         // crosses a b4 boundary (128 = 4 warps)
        const int i4 = b4 + q;
        const float4 A = X4[i4];
        float Bx = __shfl_down_sync(FULL, A.x, 1);
        float By = __shfl_down_sync(FULL, A.y, 1);
        float Bz = __shfl_down_sync(FULL, A.z, 1);
        if ((threadIdx.x & 31) == 31) {   // seam lane loads the real neighbor
            const float4 B = X4[i4 + 1];
            Bx = B.x; By = B.y; Bz = B.z;
        }
        const int rbase = (b4 * 4) * T_DIM + q * 4;
        *reinterpret_cast<float4*>(out + rbase)             = A;
        *reinterpret_cast<float4*>(out + rbase + T_DIM)     = make_float4(A.y, A.z, A.w, Bx);
        *reinterpret_cast<float4*>(out + rbase + 2 * T_DIM) = make_float4(A.z, A.w, Bx, By);
        *reinterpret_cast<float4*>(out + rbase + 3 * T_DIM) = make_float4(A.w, Bx, By, Bz);
    } else {
        const int j = gid - XTASKS;
        if (j < DTASKS) {
            const int b = j >> 4;
            const int i = j & 15;         // horizons 2i, 2i+1
            const float lvl = g_levels[b + (T_DIM - 1)];
            const float sa  = g_sseq[b + 384 + 2 * i];
            const float sb  = g_sseq[b + 385 + 2 * i];
            *reinterpret_cast<float4*>(out + B_DIM * T_DIM + b * (2 * HOR) + 4 * i) =
                make_float4(lvl, sa, lvl, sb);
        }
    }
}

// ---------------------------------------------------------------------------
// Launch. Inputs (metadata order): x, alpha, gamma, init_seasonality, level.
// ---------------------------------------------------------------------------
extern "C" void kernel_launch(void* const* d_in, const int* in_sizes, int n_in,
                              void* d_out, int out_size) {
    const float* x      = (const float*)d_in[0];
    const float* alpha  = (const float*)d_in[1];
    const float* gamma  = (const float*)d_in[2];
    const float* init_s = (const float*)d_in[3];
    const float* level  = (const float*)d_in[4];
    float* out = (float*)d_out;

    scan_kernel<<<NBLK + 1, 64>>>(x, alpha, gamma, init_s, level);
    out_kernel<<<(XTASKS + DTASKS) / 256, 256>>>(out);
}